// round 13
// baseline (speedup 1.0000x reference)
#include <cuda_runtime.h>
#include <cuda_bf16.h>

#define NP 512

// single-instruction approx reciprocal (MUFU.RCP, ~1ulp)
__device__ __forceinline__ float frcp(float x) {
    float r; asm("rcp.approx.f32 %0,%1;" : "=f"(r) : "f"(x)); return r;
}

// One block per batch element; 512 threads. Scalar diff-form math (Gram form
// is numerically unusable: catastrophic cancellation for close pairs).
//
// smem: float4 ps[768], ps[p] = (x, y, z, unused); entries 512..767 duplicate
// 0..255. One LDS.128 fetches a whole particle (was 3 LDS.32).
//
// Thread t: i = t&255, h = t>>8 (warp-uniform). Owns FOUR particles:
//   A = i, B = i+256, C = i+128, D = i+384.
// For k in [129+64h .. 192+64h], loads ps[j], ps[j+256] (j = i+k) and forms:
//   (A, j) offset k, (B, j+256) offset k, (C, j) offset k-128,
//   (D, j+256) offset k-128.
// Offsets 1..255 cover each unordered pair exactly once; offset 256
// (h=1 tail, A/B side) covers distance-256 pairs twice -> weight 1/2.
// Total LJ = 2 * sum. h is branched into two loops with LITERAL k-bases so
// addresses are reg+immediate (kills the R11 alu-pipe address overhead).
__global__ __launch_bounds__(NP, 1)
void lj_osc_kernel(const float* __restrict__ x, float* __restrict__ out) {
    __shared__ __align__(16) float4 ps[NP + 256];
    __shared__ float red[5][16];

    const int b = blockIdx.x;
    const int t = threadIdx.x;
    const int i = t & 255;
    const int h = t >> 8;
    const float* __restrict__ xb = x + (size_t)b * (NP * 3);

    float* fp = (float*)ps;

    // Coalesced load of 1536 floats; scatter into float4 slots (+duplicates).
    {
        float v0 = xb[t], v1 = xb[t + 512], v2 = xb[t + 1024];
        int e, p, d;
#define SCATTER(VAL, EE) {                                              \
        e = (EE); p = e / 3; d = e - 3 * p;                             \
        fp[4 * p + d] = VAL;                                            \
        if (p < 256) fp[4 * (p + NP) + d] = VAL; }
        SCATTER(v0, t)
        SCATTER(v1, t + 512)
        SCATTER(v2, t + 1024)
#undef SCATTER
    }
    __syncthreads();

    // Own 4 particles in registers.
    const float4 pA = ps[i];
    const float4 pB = ps[i + 256];
    const float4 pC = ps[i + 128];
    const float4 pD = ps[i + 384];

    // 8 accumulators: (Sum r^-6, Sum r^-12) per owned particle.
    float s6A = 0.f, s12A = 0.f, s6B = 0.f, s12B = 0.f;
    float s6C = 0.f, s12C = 0.f, s6D = 0.f, s12D = 0.f;
    float tacc = 0.f;

// 10 fma-pipe ops + 1 MUFU per pair.
#define PAIR(P, J, S6, S12) {                                            \
        float dx = (J).x - (P).x;                                        \
        float dy = (J).y - (P).y;                                        \
        float dz = (J).z - (P).z;                                        \
        float s  = fmaf(dx, dx, fmaf(dy, dy, fmaf(dz, dz, 1e-6f)));      \
        float r  = frcp(s);                                              \
        float r3 = r * r * r;                                            \
        S6 += r3;                                                        \
        S12 = fmaf(r3, r3, S12); }

#define QUAD(J) {                                                        \
        float4 u1 = ps[(J)];                                             \
        float4 u2 = ps[(J) + 256];                                       \
        PAIR(pA, u1, s6A, s12A)                                          \
        PAIR(pB, u2, s6B, s12B)                                          \
        PAIR(pC, u1, s6C, s12C)                                          \
        PAIR(pD, u2, s6D, s12D) }

    if (h == 0) {
        // A/B offsets 129..192, C/D offsets 1..64; all weight 1.
        #pragma unroll 8
        for (int m = 0; m < 64; ++m) {
            QUAD(i + 129 + m);
        }
    } else {
        // A/B offsets 193..255 (+256 tail), C/D offsets 65..128.
        #pragma unroll 7
        for (int m = 0; m < 63; ++m) {
            QUAD(i + 193 + m);
        }
        {   // tail k = 256: A/B weight 1/2; C/D (offset 128) weight 1.
            float4 u1 = ps[i + 256];
            float4 u2 = ps[i + 512];
            {
                float dx = u1.x - pA.x, dy = u1.y - pA.y, dz = u1.z - pA.z;
                float s  = fmaf(dx, dx, fmaf(dy, dy, fmaf(dz, dz, 1e-6f)));
                float r  = frcp(s);
                float r3 = r * r * r;
                tacc = fmaf(0.5f, fmaf(r3, r3 - 2.0f, 0.f), tacc);
            }
            {
                float dx = u2.x - pB.x, dy = u2.y - pB.y, dz = u2.z - pB.z;
                float s  = fmaf(dx, dx, fmaf(dy, dy, fmaf(dz, dz, 1e-6f)));
                float r  = frcp(s);
                float r3 = r * r * r;
                tacc = fmaf(0.5f, fmaf(r3, r3 - 2.0f, 0.f), tacc);
            }
            PAIR(pC, u1, s6C, s12C)
            PAIR(pD, u2, s6D, s12D)
        }
    }
#undef QUAD
#undef PAIR

    float sum6  = (s6A + s6B) + (s6C + s6D);
    float sum12 = (s12A + s12B) + (s12C + s12D);
    float acc = fmaf(-2.0f, sum6, sum12) + tacc;

    // Oscillator: h=0 contributes particles A (=i) and B (=i+256) -> each
    // particle exactly once.
    float sx = 0.f, sy = 0.f, sz = 0.f, ssq = 0.f;
    if (h == 0) {
        sx = pA.x + pB.x;
        sy = pA.y + pB.y;
        sz = pA.z + pB.z;
        ssq = fmaf(pA.x, pA.x, fmaf(pA.y, pA.y, pA.z * pA.z))
            + fmaf(pB.x, pB.x, fmaf(pB.y, pB.y, pB.z * pB.z));
    }

    // Block reduction of 5 values.
    float v[5] = {acc, sx, sy, sz, ssq};
    const unsigned FULL = 0xFFFFFFFFu;
    #pragma unroll
    for (int q = 0; q < 5; ++q) {
        float r = v[q];
        r += __shfl_down_sync(FULL, r, 16);
        r += __shfl_down_sync(FULL, r, 8);
        r += __shfl_down_sync(FULL, r, 4);
        r += __shfl_down_sync(FULL, r, 2);
        r += __shfl_down_sync(FULL, r, 1);
        v[q] = r;
    }
    const int warp = t >> 5;
    const int lane = t & 31;
    if (lane == 0) {
        #pragma unroll
        for (int q = 0; q < 5; ++q) red[q][warp] = v[q];
    }
    __syncthreads();
    if (warp == 0) {
        float r[5];
        #pragma unroll
        for (int q = 0; q < 5; ++q) {
            float val = (lane < 16) ? red[q][lane] : 0.0f;
            val += __shfl_down_sync(FULL, val, 8);
            val += __shfl_down_sync(FULL, val, 4);
            val += __shfl_down_sync(FULL, val, 2);
            val += __shfl_down_sync(FULL, val, 1);
            r[q] = val;
        }
        if (lane == 0) {
            float lj_total = 2.0f * r[0];
            float mean_sq = (r[1] * r[1] + r[2] * r[2] + r[3] * r[3]) * (1.0f / NP);
            float osc = 0.5f * (r[4] - mean_sq);
            out[b] = lj_total + osc;
        }
    }
}

extern "C" void kernel_launch(void* const* d_in, const int* in_sizes, int n_in,
                              void* d_out, int out_size) {
    const float* x = (const float*)d_in[0];
    float* out = (float*)d_out;
    int batches = in_sizes[0] / (NP * 3);   // 128
    lj_osc_kernel<<<batches, NP>>>(x, out);
}